// round 1
// baseline (speedup 1.0000x reference)
#include <cuda_runtime.h>
#include <cuda_bf16.h>

// Problem constants (fixed by the dataset)
#define NN 100000      // nodes
#define EE 1600000     // edges
#define GG 2000        // graphs
#define HH 128         // hidden dim
#define LL 3           // layers

// Scratch (allocation-free rule: __device__ globals)
__device__ float g_h[NN * HH];     // node features
__device__ float g_agg[NN * HH];   // aggregation buffer (init = h, scatter-adds land here)
__device__ float g_gsum[GG * HH];  // pooled sums
__device__ int   g_gcnt[GG];       // per-graph node counts

// ---------------------------------------------------------------------------
// vectorized fp32 reduction (no return) -- sm_90+
__device__ __forceinline__ void red_add_v4(float* p, float4 v) {
    asm volatile("red.global.add.v4.f32 [%0], {%1, %2, %3, %4};"
                 :: "l"(p), "f"(v.x), "f"(v.y), "f"(v.z), "f"(v.w)
                 : "memory");
}

// ---------------------------------------------------------------------------
// h = x @ proj_w + proj_b   ([N,4] @ [4,128])
__global__ void proj_kernel(const float* __restrict__ x,
                            const float* __restrict__ pw,
                            const float* __restrict__ pb,
                            float* __restrict__ h) {
    int n = blockIdx.x;
    int j = threadIdx.x;
    const float* xr = x + (size_t)n * 4;
    float x0 = xr[0], x1 = xr[1], x2 = xr[2], x3 = xr[3];
    float acc = pb[j];
    acc += x0 * pw[0 * HH + j];
    acc += x1 * pw[1 * HH + j];
    acc += x2 * pw[2 * HH + j];
    acc += x3 * pw[3 * HH + j];
    h[(size_t)n * HH + j] = acc;
}

// ---------------------------------------------------------------------------
// agg = h  (copy; scatter then accumulates on top -> agg = h + sum_{j->i} h_j)
__global__ void copy_kernel(const float4* __restrict__ src, float4* __restrict__ dst, int n4) {
    int i = blockIdx.x * blockDim.x + threadIdx.x;
    if (i < n4) dst[i] = src[i];
}

// ---------------------------------------------------------------------------
// scatter-add: one warp per edge, 32 lanes x float4 = full 128-float row
__global__ void scatter_kernel(const float* __restrict__ h,
                               const int* __restrict__ ei,   // [2,E]: src row then dst row
                               float* __restrict__ agg) {
    int w = (blockIdx.x * blockDim.x + threadIdx.x) >> 5;
    if (w >= EE) return;
    int lane = threadIdx.x & 31;
    int s = __ldg(ei + w);
    int d = __ldg(ei + EE + w);
    float4 v = ((const float4*)(h + (size_t)s * HH))[lane];
    red_add_v4(agg + (size_t)d * HH + lane * 4, v);
}

// ---------------------------------------------------------------------------
// h_out = relu( relu(m @ W1 + b1) @ W2 + b2 ),  m = agg tile
// Tile: 64 rows x 128 cols. 256 threads; thread (rb = t/32, cg = (t%32)*4)
// owns rows rb+8i (i<8), cols cg..cg+3  -> acc[8][4].
// smem: 64x128 m-tile (reused as t-tile) + 16x128 streamed W chunk = 40 KB.
__global__ void __launch_bounds__(256) mlp_kernel(
    const float* __restrict__ m_in, float* __restrict__ h_out,
    const float* __restrict__ W1, const float* __restrict__ B1,
    const float* __restrict__ W2, const float* __restrict__ B2) {
    __shared__ float sMT[64 * 128];
    __shared__ float sW[16 * 128];

    int tid  = threadIdx.x;
    int row0 = blockIdx.x * 64;
    int cg   = (tid & 31) * 4;
    int rb   = tid >> 5;

    // load m tile (zero-pad OOB rows)
    for (int i = tid; i < 64 * 32; i += 256) {
        int r = i >> 5, c = i & 31;
        int gr = row0 + r;
        float4 v = make_float4(0.f, 0.f, 0.f, 0.f);
        if (gr < NN) v = ((const float4*)(m_in + (size_t)gr * HH))[c];
        ((float4*)sMT)[r * 32 + c] = v;
    }

    float acc[8][4];
#pragma unroll
    for (int i = 0; i < 8; i++)
#pragma unroll
        for (int j = 0; j < 4; j++) acc[i][j] = 0.f;

    // ---- GEMM 1: t = m @ W1 ----
    for (int kc = 0; kc < HH; kc += 16) {
        __syncthreads();
        for (int i = tid; i < 16 * 32; i += 256)
            ((float4*)sW)[i] = ((const float4*)(W1 + (size_t)kc * HH))[i];
        __syncthreads();
#pragma unroll
        for (int k = 0; k < 16; k++) {
            float4 w = *((const float4*)(sW + k * HH + cg));
#pragma unroll
            for (int i = 0; i < 8; i++) {
                float m = sMT[(rb + 8 * i) * HH + (kc + k)];
                acc[i][0] += m * w.x; acc[i][1] += m * w.y;
                acc[i][2] += m * w.z; acc[i][3] += m * w.w;
            }
        }
    }
    __syncthreads();   // all reads of sMT (as m) done

    // t = relu(acc + b1) -> back into sMT
    {
        float b0 = B1[cg], b1v = B1[cg + 1], b2v = B1[cg + 2], b3v = B1[cg + 3];
#pragma unroll
        for (int i = 0; i < 8; i++) {
            int r = rb + 8 * i;
            float4 t;
            t.x = fmaxf(acc[i][0] + b0,  0.f);
            t.y = fmaxf(acc[i][1] + b1v, 0.f);
            t.z = fmaxf(acc[i][2] + b2v, 0.f);
            t.w = fmaxf(acc[i][3] + b3v, 0.f);
            *((float4*)(sMT + r * HH + cg)) = t;
            acc[i][0] = acc[i][1] = acc[i][2] = acc[i][3] = 0.f;
        }
    }

    // ---- GEMM 2: out = t @ W2 ----
    for (int kc = 0; kc < HH; kc += 16) {
        __syncthreads();
        for (int i = tid; i < 16 * 32; i += 256)
            ((float4*)sW)[i] = ((const float4*)(W2 + (size_t)kc * HH))[i];
        __syncthreads();
#pragma unroll
        for (int k = 0; k < 16; k++) {
            float4 w = *((const float4*)(sW + k * HH + cg));
#pragma unroll
            for (int i = 0; i < 8; i++) {
                float t = sMT[(rb + 8 * i) * HH + (kc + k)];
                acc[i][0] += t * w.x; acc[i][1] += t * w.y;
                acc[i][2] += t * w.z; acc[i][3] += t * w.w;
            }
        }
    }

    // h_out = relu(acc + b2)
    {
        float b0 = B2[cg], b1v = B2[cg + 1], b2v = B2[cg + 2], b3v = B2[cg + 3];
#pragma unroll
        for (int i = 0; i < 8; i++) {
            int gr = row0 + rb + 8 * i;
            if (gr < NN) {
                float4 o;
                o.x = fmaxf(acc[i][0] + b0,  0.f);
                o.y = fmaxf(acc[i][1] + b1v, 0.f);
                o.z = fmaxf(acc[i][2] + b2v, 0.f);
                o.w = fmaxf(acc[i][3] + b3v, 0.f);
                *((float4*)(h_out + (size_t)gr * HH + cg)) = o;
            }
        }
    }
}

// ---------------------------------------------------------------------------
__global__ void zero_pool_kernel(float* __restrict__ gsum, int* __restrict__ gcnt) {
    int i = blockIdx.x * blockDim.x + threadIdx.x;
    if (i < GG * HH) gsum[i] = 0.f;
    if (i < GG) gcnt[i] = 0;
}

// one warp per node
__global__ void pool_kernel(const float* __restrict__ h, const int* __restrict__ batch,
                            float* __restrict__ gsum, int* __restrict__ gcnt) {
    int n = (blockIdx.x * blockDim.x + threadIdx.x) >> 5;
    if (n >= NN) return;
    int lane = threadIdx.x & 31;
    int b = __ldg(batch + n);
    float4 v = ((const float4*)(h + (size_t)n * HH))[lane];
    red_add_v4(gsum + (size_t)b * HH + lane * 4, v);
    if (lane == 0) atomicAdd(gcnt + b, 1);
}

// ---------------------------------------------------------------------------
// per-graph readout: g = relu((gsum/cnt) @ Ws + bs); energy/dipole dots
__global__ void head_kernel(const float* __restrict__ gsum, const int* __restrict__ gcnt,
                            const float* __restrict__ Ws, const float* __restrict__ Bs,
                            const float* __restrict__ ew, const float* __restrict__ eb,
                            const float* __restrict__ dw, const float* __restrict__ db,
                            float* __restrict__ out) {
    int g = blockIdx.x;
    int j = threadIdx.x;
    __shared__ float sg[HH];
    __shared__ float re[HH];
    __shared__ float rd[HH];

    float cnt = fmaxf((float)gcnt[g], 1.f);
    sg[j] = gsum[(size_t)g * HH + j] / cnt;
    __syncthreads();

    float a = Bs[j];
#pragma unroll 8
    for (int k = 0; k < HH; k++) a += sg[k] * Ws[k * HH + j];
    a = fmaxf(a, 0.f);

    re[j] = a * ew[j];
    rd[j] = a * dw[j];
    __syncthreads();
    for (int s = 64; s > 0; s >>= 1) {
        if (j < s) { re[j] += re[j + s]; rd[j] += rd[j + s]; }
        __syncthreads();
    }
    if (j == 0) {
        out[g]      = re[0] + eb[0];
        out[GG + g] = rd[0] + db[0];
    }
}

// ---------------------------------------------------------------------------
extern "C" void kernel_launch(void* const* d_in, const int* in_sizes, int n_in,
                              void* d_out, int out_size) {
    const float* x       = (const float*)d_in[0];
    const int*   ei      = (const int*)  d_in[1];
    const int*   batch   = (const int*)  d_in[2];
    const float* proj_w  = (const float*)d_in[3];
    const float* proj_b  = (const float*)d_in[4];
    const float* conv_w1 = (const float*)d_in[5];
    const float* conv_b1 = (const float*)d_in[6];
    const float* conv_w2 = (const float*)d_in[7];
    const float* conv_b2 = (const float*)d_in[8];
    const float* sh_w    = (const float*)d_in[9];
    const float* sh_b    = (const float*)d_in[10];
    const float* e_w     = (const float*)d_in[11];
    const float* e_b     = (const float*)d_in[12];
    const float* d_w     = (const float*)d_in[13];
    const float* d_b     = (const float*)d_in[14];
    float* out = (float*)d_out;

    float* h   = nullptr;
    float* agg = nullptr;
    float* gsum = nullptr;
    int*   gcnt = nullptr;
    cudaGetSymbolAddress((void**)&h,    g_h);
    cudaGetSymbolAddress((void**)&agg,  g_agg);
    cudaGetSymbolAddress((void**)&gsum, g_gsum);
    cudaGetSymbolAddress((void**)&gcnt, g_gcnt);

    // input projection
    proj_kernel<<<NN, HH>>>(x, proj_w, proj_b, h);

    const int n4 = NN * HH / 4;                       // 3.2M float4
    const int copy_blocks = (n4 + 255) / 256;
    const int scat_blocks = (EE * 32 + 255) / 256;    // one warp per edge
    const int mlp_blocks  = (NN + 63) / 64;

    for (int l = 0; l < LL; l++) {
        copy_kernel<<<copy_blocks, 256>>>((const float4*)h, (float4*)agg, n4);
        scatter_kernel<<<scat_blocks, 256>>>(h, ei, agg);
        mlp_kernel<<<mlp_blocks, 256>>>(agg, h,
                                        conv_w1 + (size_t)l * HH * HH,
                                        conv_b1 + (size_t)l * HH,
                                        conv_w2 + (size_t)l * HH * HH,
                                        conv_b2 + (size_t)l * HH);
    }

    zero_pool_kernel<<<(GG * HH + 255) / 256, 256>>>(gsum, gcnt);
    pool_kernel<<<(NN * 32 + 255) / 256, 256>>>(h, batch, gsum, gcnt);
    head_kernel<<<GG, HH>>>(gsum, gcnt, sh_w, sh_b, e_w, e_b, d_w, d_b, out);
}

// round 2
// speedup vs baseline: 1.1007x; 1.1007x over previous
#include <cuda_runtime.h>
#include <cuda_bf16.h>

#define NN 100000
#define EE 1600000
#define GG 2000
#define HH 128
#define LL 3
#define SCAN_B 512
#define SCAN_NB ((NN + SCAN_B - 1) / SCAN_B)   // 196

// Scratch (__device__ globals; no allocations allowed)
__device__ float g_h [NN * HH];
__device__ float g_h2[NN * HH];
__device__ int   g_deg[NN];
__device__ int   g_off[NN];
__device__ int   g_cur[NN];
__device__ int   g_csr[EE];
__device__ int   g_bsum[256];
__device__ int   g_bpre[256];
__device__ float g_gsum[GG * HH];
__device__ int   g_gcnt[GG];

__device__ __forceinline__ void red_add_v4(float* p, float4 v) {
    asm volatile("red.global.add.v4.f32 [%0], {%1, %2, %3, %4};"
                 :: "l"(p), "f"(v.x), "f"(v.y), "f"(v.z), "f"(v.w)
                 : "memory");
}

// ---------------------------------------------------------------------------
// h = x @ proj_w + proj_b   ([N,4] @ [4,128])
__global__ void proj_kernel(const float* __restrict__ x,
                            const float* __restrict__ pw,
                            const float* __restrict__ pb,
                            float* __restrict__ h) {
    int n = blockIdx.x;
    int j = threadIdx.x;
    const float* xr = x + (size_t)n * 4;
    float acc = pb[j];
    acc += xr[0] * pw[0 * HH + j];
    acc += xr[1] * pw[1 * HH + j];
    acc += xr[2] * pw[2 * HH + j];
    acc += xr[3] * pw[3 * HH + j];
    h[(size_t)n * HH + j] = acc;
}

// ---------------------------------------------------------------------------
// CSR build: histogram -> scan -> fill
__global__ void zero_deg_kernel(int* __restrict__ deg) {
    int i = blockIdx.x * blockDim.x + threadIdx.x;
    if (i < NN) deg[i] = 0;
}

__global__ void hist_kernel(const int* __restrict__ ei, int* __restrict__ deg) {
    int e = blockIdx.x * blockDim.x + threadIdx.x;
    if (e < EE) atomicAdd(deg + __ldg(ei + EE + e), 1);
}

// per-block exclusive scan + block totals
__global__ void scan1_kernel(const int* __restrict__ deg,
                             int* __restrict__ part, int* __restrict__ bsum) {
    __shared__ int s[SCAN_B];
    int t = threadIdx.x;
    int i = blockIdx.x * SCAN_B + t;
    int v = (i < NN) ? deg[i] : 0;
    s[t] = v;
    __syncthreads();
    for (int o = 1; o < SCAN_B; o <<= 1) {
        int x = (t >= o) ? s[t - o] : 0;
        __syncthreads();
        s[t] += x;
        __syncthreads();
    }
    if (i < NN) part[i] = s[t] - v;           // exclusive within block
    if (t == SCAN_B - 1) bsum[blockIdx.x] = s[t];
}

__global__ void scan2_kernel(const int* __restrict__ bsum, int* __restrict__ bpre) {
    __shared__ int s[256];
    int t = threadIdx.x;
    int v = (t < SCAN_NB) ? bsum[t] : 0;
    s[t] = v;
    __syncthreads();
    for (int o = 1; o < 256; o <<= 1) {
        int x = (t >= o) ? s[t - o] : 0;
        __syncthreads();
        s[t] += x;
        __syncthreads();
    }
    if (t < SCAN_NB) bpre[t] = s[t] - v;      // exclusive across blocks
}

__global__ void scan3_kernel(int* __restrict__ off, const int* __restrict__ bpre,
                             int* __restrict__ cur) {
    int i = blockIdx.x * blockDim.x + threadIdx.x;
    if (i < NN) {
        int o = off[i] + bpre[i / SCAN_B];
        off[i] = o;
        cur[i] = o;
    }
}

__global__ void fill_kernel(const int* __restrict__ ei,
                            int* __restrict__ cur, int* __restrict__ csr) {
    int e = blockIdx.x * blockDim.x + threadIdx.x;
    if (e < EE) {
        int s = __ldg(ei + e);
        int d = __ldg(ei + EE + e);
        int p = atomicAdd(cur + d, 1);
        csr[p] = s;
    }
}

// ---------------------------------------------------------------------------
// Fused: m = h + sum_nbr h  (CSR gather), then h_out = relu(relu(m@W1+b1)@W2+b2)
// 64-row tile; 256 threads. GEMM blocking: thread (rb=tid>>4, cg=(tid&15)*8)
// owns rows rb+16i (i<4), cols cg..cg+7 -> acc[4][8].
// smem: 64x128 tile (32KB) + 32x128 W chunk (16KB) = 48KB.
__global__ void __launch_bounds__(256) mlp_fused_kernel(
    const float* __restrict__ in, float* __restrict__ out,
    const int* __restrict__ off, const int* __restrict__ deg,
    const int* __restrict__ csr,
    const float* __restrict__ W1, const float* __restrict__ B1,
    const float* __restrict__ W2, const float* __restrict__ B2) {
    __shared__ float sMT[64 * HH];
    __shared__ float sW[32 * HH];

    int tid  = threadIdx.x;
    int lane = tid & 31;
    int wrp  = tid >> 5;
    int row0 = blockIdx.x * 64;

    // ---- gather phase: warp wrp handles rows wrp*8 .. wrp*8+7 ----
#pragma unroll
    for (int j = 0; j < 8; j++) {
        int r = wrp * 8 + j;
        int n = row0 + r;
        float4 acc = make_float4(0.f, 0.f, 0.f, 0.f);
        if (n < NN) {
            acc = __ldg((const float4*)(in + (size_t)n * HH) + lane);
            int e0 = __ldg(off + n);
            int d  = __ldg(deg + n);
#pragma unroll 4
            for (int e = 0; e < d; e++) {
                int s = __ldg(csr + e0 + e);
                float4 v = __ldg((const float4*)(in + (size_t)s * HH) + lane);
                acc.x += v.x; acc.y += v.y; acc.z += v.z; acc.w += v.w;
            }
        }
        ((float4*)(sMT + r * HH))[lane] = acc;
    }

    int rb = tid >> 4;            // 0..15
    int cg = (tid & 15) * 8;      // 0..120 step 8

    float acc[4][8];
#pragma unroll
    for (int i = 0; i < 4; i++)
#pragma unroll
        for (int j = 0; j < 8; j++) acc[i][j] = 0.f;

    // ---- GEMM 1: t = m @ W1 ----
    for (int kc = 0; kc < HH; kc += 32) {
        __syncthreads();
        for (int i = tid; i < 32 * 32; i += 256)
            ((float4*)sW)[i] = ((const float4*)(W1 + (size_t)kc * HH))[i];
        __syncthreads();
#pragma unroll
        for (int k = 0; k < 32; k++) {
            float4 w0 = *(const float4*)(sW + k * HH + cg);
            float4 w1 = *(const float4*)(sW + k * HH + cg + 4);
#pragma unroll
            for (int i = 0; i < 4; i++) {
                float m = sMT[(rb + 16 * i) * HH + kc + k];
                acc[i][0] += m * w0.x; acc[i][1] += m * w0.y;
                acc[i][2] += m * w0.z; acc[i][3] += m * w0.w;
                acc[i][4] += m * w1.x; acc[i][5] += m * w1.y;
                acc[i][6] += m * w1.z; acc[i][7] += m * w1.w;
            }
        }
    }
    __syncthreads();

    // t = relu(acc + b1) -> sMT
    {
        float4 b0 = *(const float4*)(B1 + cg);
        float4 b1 = *(const float4*)(B1 + cg + 4);
#pragma unroll
        for (int i = 0; i < 4; i++) {
            int r = rb + 16 * i;
            float4 t0, t1;
            t0.x = fmaxf(acc[i][0] + b0.x, 0.f);
            t0.y = fmaxf(acc[i][1] + b0.y, 0.f);
            t0.z = fmaxf(acc[i][2] + b0.z, 0.f);
            t0.w = fmaxf(acc[i][3] + b0.w, 0.f);
            t1.x = fmaxf(acc[i][4] + b1.x, 0.f);
            t1.y = fmaxf(acc[i][5] + b1.y, 0.f);
            t1.z = fmaxf(acc[i][6] + b1.z, 0.f);
            t1.w = fmaxf(acc[i][7] + b1.w, 0.f);
            *(float4*)(sMT + r * HH + cg)     = t0;
            *(float4*)(sMT + r * HH + cg + 4) = t1;
#pragma unroll
            for (int j = 0; j < 8; j++) acc[i][j] = 0.f;
        }
    }

    // ---- GEMM 2: o = t @ W2 ----
    for (int kc = 0; kc < HH; kc += 32) {
        __syncthreads();
        for (int i = tid; i < 32 * 32; i += 256)
            ((float4*)sW)[i] = ((const float4*)(W2 + (size_t)kc * HH))[i];
        __syncthreads();
#pragma unroll
        for (int k = 0; k < 32; k++) {
            float4 w0 = *(const float4*)(sW + k * HH + cg);
            float4 w1 = *(const float4*)(sW + k * HH + cg + 4);
#pragma unroll
            for (int i = 0; i < 4; i++) {
                float t = sMT[(rb + 16 * i) * HH + kc + k];
                acc[i][0] += t * w0.x; acc[i][1] += t * w0.y;
                acc[i][2] += t * w0.z; acc[i][3] += t * w0.w;
                acc[i][4] += t * w1.x; acc[i][5] += t * w1.y;
                acc[i][6] += t * w1.z; acc[i][7] += t * w1.w;
            }
        }
    }

    // h_out = relu(acc + b2)
    {
        float4 b0 = *(const float4*)(B2 + cg);
        float4 b1 = *(const float4*)(B2 + cg + 4);
#pragma unroll
        for (int i = 0; i < 4; i++) {
            int n = row0 + rb + 16 * i;
            if (n < NN) {
                float4 o0, o1;
                o0.x = fmaxf(acc[i][0] + b0.x, 0.f);
                o0.y = fmaxf(acc[i][1] + b0.y, 0.f);
                o0.z = fmaxf(acc[i][2] + b0.z, 0.f);
                o0.w = fmaxf(acc[i][3] + b0.w, 0.f);
                o1.x = fmaxf(acc[i][4] + b1.x, 0.f);
                o1.y = fmaxf(acc[i][5] + b1.y, 0.f);
                o1.z = fmaxf(acc[i][6] + b1.z, 0.f);
                o1.w = fmaxf(acc[i][7] + b1.w, 0.f);
                *(float4*)(out + (size_t)n * HH + cg)     = o0;
                *(float4*)(out + (size_t)n * HH + cg + 4) = o1;
            }
        }
    }
}

// ---------------------------------------------------------------------------
__global__ void zero_pool_kernel(float* __restrict__ gsum, int* __restrict__ gcnt) {
    int i = blockIdx.x * blockDim.x + threadIdx.x;
    if (i < GG * HH) gsum[i] = 0.f;
    if (i < GG) gcnt[i] = 0;
}

__global__ void pool_kernel(const float* __restrict__ h, const int* __restrict__ batch,
                            float* __restrict__ gsum, int* __restrict__ gcnt) {
    int n = (blockIdx.x * blockDim.x + threadIdx.x) >> 5;
    if (n >= NN) return;
    int lane = threadIdx.x & 31;
    int b = __ldg(batch + n);
    float4 v = ((const float4*)(h + (size_t)n * HH))[lane];
    red_add_v4(gsum + (size_t)b * HH + lane * 4, v);
    if (lane == 0) atomicAdd(gcnt + b, 1);
}

// ---------------------------------------------------------------------------
__global__ void head_kernel(const float* __restrict__ gsum, const int* __restrict__ gcnt,
                            const float* __restrict__ Ws, const float* __restrict__ Bs,
                            const float* __restrict__ ew, const float* __restrict__ eb,
                            const float* __restrict__ dw, const float* __restrict__ db,
                            float* __restrict__ out) {
    int g = blockIdx.x;
    int j = threadIdx.x;
    __shared__ float sg[HH];
    __shared__ float re[HH];
    __shared__ float rd[HH];

    float cnt = fmaxf((float)gcnt[g], 1.f);
    sg[j] = gsum[(size_t)g * HH + j] / cnt;
    __syncthreads();

    float a = Bs[j];
#pragma unroll 8
    for (int k = 0; k < HH; k++) a += sg[k] * Ws[k * HH + j];
    a = fmaxf(a, 0.f);

    re[j] = a * ew[j];
    rd[j] = a * dw[j];
    __syncthreads();
    for (int s = 64; s > 0; s >>= 1) {
        if (j < s) { re[j] += re[j + s]; rd[j] += rd[j + s]; }
        __syncthreads();
    }
    if (j == 0) {
        out[g]      = re[0] + eb[0];
        out[GG + g] = rd[0] + db[0];
    }
}

// ---------------------------------------------------------------------------
extern "C" void kernel_launch(void* const* d_in, const int* in_sizes, int n_in,
                              void* d_out, int out_size) {
    const float* x       = (const float*)d_in[0];
    const int*   ei      = (const int*)  d_in[1];
    const int*   batch   = (const int*)  d_in[2];
    const float* proj_w  = (const float*)d_in[3];
    const float* proj_b  = (const float*)d_in[4];
    const float* conv_w1 = (const float*)d_in[5];
    const float* conv_b1 = (const float*)d_in[6];
    const float* conv_w2 = (const float*)d_in[7];
    const float* conv_b2 = (const float*)d_in[8];
    const float* sh_w    = (const float*)d_in[9];
    const float* sh_b    = (const float*)d_in[10];
    const float* e_w     = (const float*)d_in[11];
    const float* e_b     = (const float*)d_in[12];
    const float* d_w     = (const float*)d_in[13];
    const float* d_b     = (const float*)d_in[14];
    float* out = (float*)d_out;

    float *h, *h2, *gsum;
    int *deg, *off, *cur, *csr, *bsum, *bpre, *gcnt;
    cudaGetSymbolAddress((void**)&h,    g_h);
    cudaGetSymbolAddress((void**)&h2,   g_h2);
    cudaGetSymbolAddress((void**)&deg,  g_deg);
    cudaGetSymbolAddress((void**)&off,  g_off);
    cudaGetSymbolAddress((void**)&cur,  g_cur);
    cudaGetSymbolAddress((void**)&csr,  g_csr);
    cudaGetSymbolAddress((void**)&bsum, g_bsum);
    cudaGetSymbolAddress((void**)&bpre, g_bpre);
    cudaGetSymbolAddress((void**)&gsum, g_gsum);
    cudaGetSymbolAddress((void**)&gcnt, g_gcnt);

    // input projection
    proj_kernel<<<NN, HH>>>(x, proj_w, proj_b, h);

    // CSR build (edges grouped by destination)
    zero_deg_kernel<<<(NN + 255) / 256, 256>>>(deg);
    hist_kernel<<<(EE + 255) / 256, 256>>>(ei, deg);
    scan1_kernel<<<SCAN_NB, SCAN_B>>>(deg, off, bsum);
    scan2_kernel<<<1, 256>>>(bsum, bpre);
    scan3_kernel<<<(NN + 255) / 256, 256>>>(off, bpre, cur);
    fill_kernel<<<(EE + 255) / 256, 256>>>(ei, cur, csr);

    // GIN layers (ping-pong h <-> h2)
    const int mlp_blocks = (NN + 63) / 64;
    const float* src = h;
    float* dst = h2;
    for (int l = 0; l < LL; l++) {
        mlp_fused_kernel<<<mlp_blocks, 256>>>(src, dst, off, deg, csr,
                                              conv_w1 + (size_t)l * HH * HH,
                                              conv_b1 + (size_t)l * HH,
                                              conv_w2 + (size_t)l * HH * HH,
                                              conv_b2 + (size_t)l * HH);
        const float* t = dst; dst = (float*)src; src = t;
    }
    // after 3 layers result is in h2 (h->h2->h->h2); src points at it
    const float* hf = src;

    zero_pool_kernel<<<(GG * HH + 255) / 256, 256>>>(gsum, gcnt);
    pool_kernel<<<(NN * 32 + 255) / 256, 256>>>(hf, batch, gsum, gcnt);
    head_kernel<<<GG, HH>>>(gsum, gcnt, sh_w, sh_b, e_w, e_b, d_w, d_b, out);
}